// round 12
// baseline (speedup 1.0000x reference)
#include <cuda_runtime.h>

#define N_NODES    262144
#define N_EDGES    4194304
#define NUM_GRAPHS 1024

typedef unsigned long long u64;

// ---------------- scratch (device globals; no allocations allowed) ----------
struct __align__(32) NodeRec {
    float4 x;    // node features
    float4 pos;  // padded position (w unused)
};
__device__ NodeRec g_rec[N_NODES];            // packed per-node record
__device__ int     g_hist[N_NODES];           // in-degree histogram
__device__ int     g_off[N_NODES + 1];        // CSR offsets (exclusive scan)
__device__ int     g_cursor[N_NODES];         // scatter cursors
__device__ int     g_bsum[256];               // per-block scan sums
__device__ int     g_bpre[256];               // exclusive block prefix
__device__ int     g_sorted_src[N_EDGES];     // src index sorted by dst
__device__ float4  g_pooled[NUM_GRAPHS * 8];  // pooled: (NUM_GRAPHS, 2, 16)

// ---------------- packed f32x2 helpers ----------------
__device__ __forceinline__ u64 pack2(float lo, float hi) {
    u64 r; asm("mov.b64 %0, {%1,%2};" : "=l"(r) : "f"(lo), "f"(hi)); return r;
}
__device__ __forceinline__ void unpack2(u64 v, float& lo, float& hi) {
    asm("mov.b64 {%0,%1}, %2;" : "=f"(lo), "=f"(hi) : "l"(v));
}
__device__ __forceinline__ u64 fma2(u64 a, u64 b, u64 c) {
    u64 d; asm("fma.rn.f32x2 %0, %1, %2, %3;" : "=l"(d) : "l"(a), "l"(b), "l"(c)); return d;
}

// SiLU via single-MUFU tanh: silu(u) = 0.5u * (1 + tanh(u/2))
__device__ __forceinline__ float silu_f(float u) {
    float hu = 0.5f * u;
    float th; asm("tanh.approx.f32 %0, %1;" : "=f"(th) : "f"(hu));
    return fmaf(hu, th, hu);
}

__device__ __forceinline__ void red_add_v4(float4* addr, float a, float b, float c, float d) {
    asm volatile("red.global.add.v4.f32 [%0], {%1,%2,%3,%4};"
                 :: "l"(addr), "f"(a), "f"(b), "f"(c), "f"(d) : "memory");
}
__device__ __forceinline__ void red_add_f(float* addr, float v) {
    asm volatile("red.global.add.f32 [%0], %1;" :: "l"(addr), "f"(v) : "memory");
}
__device__ __forceinline__ void red_add_i(int* addr, int v) {
    asm volatile("red.global.add.s32 [%0], %1;" :: "l"(addr), "r"(v) : "memory");
}

// ---------------- kernel 0: build record + zero hist/pooled ------------------
__global__ void __launch_bounds__(256) pre_kernel(
    const float* __restrict__ x, const float* __restrict__ pos)
{
    int n = blockIdx.x * 256 + threadIdx.x;
    if (n >= N_NODES) return;
    NodeRec r;
    r.x   = reinterpret_cast<const float4*>(x)[n];
    r.pos = make_float4(pos[3 * n], pos[3 * n + 1], pos[3 * n + 2], 0.f);
    g_rec[n] = r;
    g_hist[n] = 0;
    if (n < NUM_GRAPHS * 8) g_pooled[n] = make_float4(0.f, 0.f, 0.f, 0.f);
}

// ---------------- kernel 1: histogram of dst ---------------------------------
__global__ void __launch_bounds__(256) hist_kernel(const int* __restrict__ ei)
{
    int i = blockIdx.x * 256 + threadIdx.x;          // i indexes groups of 4
    int4 d4 = reinterpret_cast<const int4*>(ei + N_EDGES)[i];
    red_add_i(&g_hist[d4.x], 1);
    red_add_i(&g_hist[d4.y], 1);
    red_add_i(&g_hist[d4.z], 1);
    red_add_i(&g_hist[d4.w], 1);
}

// ---------------- kernel 2a: per-block inclusive scan (1024/block) -----------
__global__ void __launch_bounds__(1024) scanA_kernel()
{
    __shared__ int sh[1024];
    int t = threadIdx.x;
    int i = blockIdx.x * 1024 + t;
    sh[t] = g_hist[i];
    __syncthreads();
#pragma unroll
    for (int off = 1; off < 1024; off <<= 1) {
        int v = 0;
        if (t >= off) v = sh[t - off];
        __syncthreads();
        if (t >= off) sh[t] += v;
        __syncthreads();
    }
    g_off[i] = sh[t];                      // inclusive within block (temp)
    if (t == 1023) g_bsum[blockIdx.x] = sh[1023];
}

// ---------------- kernel 2b: scan the 256 block sums -------------------------
__global__ void __launch_bounds__(256) scanB_kernel()
{
    __shared__ int sh[256];
    int t = threadIdx.x;
    sh[t] = g_bsum[t];
    __syncthreads();
#pragma unroll
    for (int off = 1; off < 256; off <<= 1) {
        int v = 0;
        if (t >= off) v = sh[t - off];
        __syncthreads();
        if (t >= off) sh[t] += v;
        __syncthreads();
    }
    g_bpre[t] = sh[t] - g_bsum[t];         // exclusive prefix of block sums
}

// ---------------- kernel 2c: finalize exclusive offsets + cursors ------------
__global__ void __launch_bounds__(256) scanC_kernel()
{
    int i = blockIdx.x * 256 + threadIdx.x;
    if (i >= N_NODES) return;
    int excl = g_off[i] - g_hist[i] + g_bpre[i >> 10];
    g_off[i] = excl;
    g_cursor[i] = excl;
    if (i == 0) g_off[N_NODES] = N_EDGES;
}

// ---------------- kernel 3: reorder src by dst -------------------------------
__global__ void __launch_bounds__(256) reorder_kernel(const int* __restrict__ ei)
{
    int e = blockIdx.x * 256 + threadIdx.x;
    int s = ei[e];
    int d = ei[N_EDGES + e];
    int p = atomicAdd(&g_cursor[d], 1);
    g_sorted_src[p] = s;
}

// ---------------- kernel 4: fused node kernel (warp per node) ----------------
// layer1+silu per edge, warp reduce, W2 on node side, relu/softmax, pooling.
__global__ void __launch_bounds__(256) nodeB_kernel(
    const int* __restrict__ batch,
    const float* __restrict__ w1, const float* __restrict__ b1,
    const float* __restrict__ w2, const float* __restrict__ b2,
    const float* __restrict__ pool_w, const float* __restrict__ pool_b,
    float* __restrict__ out_s)
{
    __shared__ __align__(16) float spool[32];   // MUST be 16B-aligned (float4 read below)
    __shared__ u64   sw1p[72];   // 9 rows x 8 channel-pairs
    __shared__ u64   sb1p[8];
    __shared__ float sw2[256];   // (16,16) row-major
    __shared__ float sb2[16];
    __shared__ float spw[32];
    __shared__ float spb[2];
    __shared__ int   sgfirst;

    int t = threadIdx.x;
    if (t < 72)       sw1p[t] = pack2(w1[2 * t], w1[2 * t + 1]);
    else if (t < 80)  sb1p[t - 72] = pack2(b1[2 * (t - 72)], b1[2 * (t - 72) + 1]);
    if (t < 256)      sw2[t] = w2[t];
    if (t < 16)       sb2[t] = b2[t];
    if (t >= 16 && t < 48) spw[t - 16] = pool_w[t - 16];
    if (t == 48)      { spb[0] = pool_b[0]; spb[1] = pool_b[1]; }
    if (t < 32)       spool[t] = 0.f;
    if (t == 0)       sgfirst = batch[blockIdx.x * 8];
    __syncthreads();

    const unsigned full = 0xffffffffu;
    int warp = t >> 5;
    int lane = t & 31;
    int n = blockIdx.x * 8 + warp;

    int beg = g_off[n];
    int end = g_off[n + 1];
    int cnt = end - beg;

    NodeRec rd = g_rec[n];   // same address across warp -> broadcast

    // base = b1 + x_dst @ w1[0:4]  (packed pairs; uniform across warp)
    u64 base[8];
    {
        u64 fx = pack2(rd.x.x, rd.x.x);
        u64 fy = pack2(rd.x.y, rd.x.y);
        u64 fz = pack2(rd.x.z, rd.x.z);
        u64 fw = pack2(rd.x.w, rd.x.w);
#pragma unroll
        for (int j = 0; j < 8; j++) {
            u64 a = sb1p[j];
            a = fma2(fx, sw1p[0 * 8 + j], a);
            a = fma2(fy, sw1p[1 * 8 + j], a);
            a = fma2(fz, sw1p[2 * 8 + j], a);
            a = fma2(fw, sw1p[3 * 8 + j], a);
            base[j] = a;
        }
    }

    // accumulate S = sum over edges of silu(hid)
    float S[16];
#pragma unroll
    for (int j = 0; j < 16; j++) S[j] = 0.f;

    for (int i0 = beg; i0 < end; i0 += 32) {
        int i = i0 + lane;
        if (i < end) {
            int s = g_sorted_src[i];
            NodeRec rs = g_rec[s];
            float rx = rs.pos.x - rd.pos.x;
            float ry = rs.pos.y - rd.pos.y;
            float rz = rs.pos.z - rd.pos.z;
            float dist = sqrtf(fmaf(rx, rx, fmaf(ry, ry, rz * rz)));

            u64 fx = pack2(rs.x.x, rs.x.x);
            u64 fy = pack2(rs.x.y, rs.x.y);
            u64 fz = pack2(rs.x.z, rs.x.z);
            u64 fw = pack2(rs.x.w, rs.x.w);
            u64 dd = pack2(dist, dist);

            u64 acc[8];
#pragma unroll
            for (int j = 0; j < 8; j++) {
                u64 a = base[j];
                a = fma2(fx, sw1p[4 * 8 + j], a);
                a = fma2(fy, sw1p[5 * 8 + j], a);
                a = fma2(fz, sw1p[6 * 8 + j], a);
                a = fma2(fw, sw1p[7 * 8 + j], a);
                a = fma2(dd, sw1p[8 * 8 + j], a);
                acc[j] = a;
            }
#pragma unroll
            for (int j = 0; j < 8; j++) {
                float a, b;
                unpack2(acc[j], a, b);
                S[2 * j + 0] += silu_f(a);
                S[2 * j + 1] += silu_f(b);
            }
        }
    }

    // warp reduction of 16 channels (every lane ends with full sums)
#pragma unroll
    for (int j = 0; j < 16; j++) {
        float sv = S[j];
        sv += __shfl_xor_sync(full, sv, 16);
        sv += __shfl_xor_sync(full, sv, 8);
        sv += __shfl_xor_sync(full, sv, 4);
        sv += __shfl_xor_sync(full, sv, 2);
        sv += __shfl_xor_sync(full, sv, 1);
        S[j] = sv;
    }

    // node-side W2: lane j<16 computes channel j
    float h = 0.f;
    float fc = (float)cnt;
    float inv = __frcp_rn(fmaxf(fc, 1.0f));
    if (lane < 16) {
        float num = fc * sb2[lane];
#pragma unroll
        for (int i = 0; i < 16; i++)
            num = fmaf(S[i], sw2[i * 16 + lane], num);
        h = fmaxf(num * inv, 0.f);
    }

    // logits via cross-lane reduce (upper lanes contribute 0)
    float c0 = 0.f, c1 = 0.f;
    if (lane < 16) {
        c0 = h * spw[2 * lane + 0];
        c1 = h * spw[2 * lane + 1];
    }
#pragma unroll
    for (int off = 16; off >= 1; off >>= 1) {
        c0 += __shfl_xor_sync(full, c0, off);
        c1 += __shfl_xor_sync(full, c1, off);
    }
    float l0 = c0 + spb[0], l1 = c1 + spb[1];
    float mm = fmaxf(l0, l1);
    float e0 = __expf(l0 - mm), e1 = __expf(l1 - mm);
    float is = __frcp_rn(e0 + e1);
    float s0 = e0 * is, s1 = e1 * is;

    if (lane == 0) reinterpret_cast<float2*>(out_s)[n] = make_float2(s0, s1);

    // pooled contribution: lane j<16 -> s0*h_j at slot j; lane j>=16 -> s1*h_{j-16} at slot j
    float hup = __shfl_xor_sync(full, h, 16);   // lanes >=16 receive h of lane-16 partner
    float val = (lane < 16) ? s0 * h : s1 * hup;

    int g = batch[n];   // same address across warp -> broadcast
    if (g == sgfirst) {
        atomicAdd(&spool[lane], val);
    } else {
        red_add_f(&reinterpret_cast<float*>(g_pooled)[g * 32 + lane], val);
    }

    __syncthreads();
    if (t < 8) {
        float4 v = *reinterpret_cast<float4*>(&spool[4 * t]);
        red_add_v4(&g_pooled[sgfirst * 8 + t], v.x, v.y, v.z, v.w);
    }
}

// ---------------- kernel 5: per-graph head (one warp per graph) -------------
__global__ void __launch_bounds__(32) graph_kernel(
    const float* __restrict__ toz_w, const float* __restrict__ toz_b,
    const float* __restrict__ vp_w1, const float* __restrict__ vp_b1,
    const float* __restrict__ vp_w2, const float* __restrict__ vp_b2,
    const float* __restrict__ bridge_w, const float* __restrict__ bridge_b,
    float* __restrict__ out_recon,   // (1024, 8, 4)
    float* __restrict__ out_z,       // (1024, 2, 4)
    float* __restrict__ out_forces,  // (1024, 2, 2)
    float* __restrict__ out_V)       // (1024, 1)
{
    const unsigned full = 0xffffffffu;
    int g = blockIdx.x;
    int l = threadIdx.x;
    int k = l >> 4;
    int idx = l & 15;

    float p = reinterpret_cast<const float*>(&g_pooled[g * 8])[l];

    float z[8];
#pragma unroll
    for (int c = 0; c < 4; c++) {
        float prod = p * toz_w[idx * 4 + c];
        prod += __shfl_xor_sync(full, prod, 8);
        prod += __shfl_xor_sync(full, prod, 4);
        prod += __shfl_xor_sync(full, prod, 2);
        prod += __shfl_xor_sync(full, prod, 1);
        float zo = prod + toz_b[c];
        float zx = __shfl_xor_sync(full, zo, 16);
        z[k * 4 + c] = zo;
        z[(1 - k) * 4 + c] = zx;
    }

    if (l < 8) out_z[g * 8 + l] = z[l];

    {
        float acc = bridge_b[l];
#pragma unroll
        for (int i = 0; i < 8; i++)
            acc = fmaf(z[i], bridge_w[i * 32 + l], acc);
        out_recon[g * 32 + l] = acc;
    }

    float dx = z[0] - z[4];
    float dy = z[1] - z[5];
    float dist = sqrtf(dx * dx + dy * dy + 1e-6f);

    float w1 = vp_w1[l];
    float w2 = vp_w2[l];
    float tt = fmaf(dist, w1, vp_b1[l]);
    float u  = __expf(-fabsf(tt));
    float sp = fmaxf(tt, 0.f) + __logf(1.f + u);
    float Vp = sp * w2;
    float sig = __frcp_rn(1.f + __expf(-tt));
    float fpp = sig * w1 * w2;

#pragma unroll
    for (int off = 16; off >= 1; off >>= 1) {
        Vp  += __shfl_xor_sync(full, Vp,  off);
        fpp += __shfl_xor_sync(full, fpp, off);
    }

    if (l == 0) {
        float c = fpp / dist;
        out_forces[g * 4 + 0] = -c * dx;
        out_forces[g * 4 + 1] = -c * dy;
        out_forces[g * 4 + 2] =  c * dx;
        out_forces[g * 4 + 3] =  c * dy;
        out_V[g] = Vp + vp_b2[0];
    }
}

// ---------------- launch -----------------------------------------------------
extern "C" void kernel_launch(void* const* d_in, const int* in_sizes, int n_in,
                              void* d_out, int out_size)
{
    const float* x        = (const float*)d_in[0];
    const float* pos      = (const float*)d_in[1];
    const int*   ei       = (const int*)  d_in[2];
    const int*   batch    = (const int*)  d_in[3];
    const float* enc_w1   = (const float*)d_in[4];
    const float* enc_b1   = (const float*)d_in[5];
    const float* enc_w2   = (const float*)d_in[6];
    const float* enc_b2   = (const float*)d_in[7];
    const float* pool_w   = (const float*)d_in[8];
    const float* pool_b   = (const float*)d_in[9];
    const float* toz_w    = (const float*)d_in[10];
    const float* toz_b    = (const float*)d_in[11];
    const float* vp_w1    = (const float*)d_in[12];
    const float* vp_b1    = (const float*)d_in[13];
    const float* vp_w2    = (const float*)d_in[14];
    const float* vp_b2    = (const float*)d_in[15];
    const float* bridge_w = (const float*)d_in[16];
    const float* bridge_b = (const float*)d_in[17];

    float* out = (float*)d_out;
    float* out_recon  = out;                 // 1024*8*4 = 32768
    float* out_z      = out + 32768;         // 1024*2*4 =  8192
    float* out_s      = out + 40960;         // 262144*2 = 524288
    float* out_forces = out + 565248;        // 1024*2*2 =  4096
    float* out_V      = out + 569344;        // 1024

    pre_kernel<<<N_NODES / 256, 256>>>(x, pos);

    hist_kernel<<<N_EDGES / 4 / 256, 256>>>(ei);

    scanA_kernel<<<N_NODES / 1024, 1024>>>();
    scanB_kernel<<<1, 256>>>();
    scanC_kernel<<<N_NODES / 256, 256>>>();

    reorder_kernel<<<N_EDGES / 256, 256>>>(ei);

    // 8 nodes per block (8 warps of 32), so N_NODES/8 blocks
    nodeB_kernel<<<N_NODES / 8, 256>>>(batch, enc_w1, enc_b1, enc_w2, enc_b2,
                                       pool_w, pool_b, out_s);

    graph_kernel<<<NUM_GRAPHS, 32>>>(toz_w, toz_b, vp_w1, vp_b1, vp_w2, vp_b2,
                                     bridge_w, bridge_b,
                                     out_recon, out_z, out_forces, out_V);
}

// round 13
// speedup vs baseline: 4.1375x; 4.1375x over previous
#include <cuda_runtime.h>
#include <cuda_fp16.h>

#define N_NODES    262144
#define N_EDGES    4194304
#define NUM_GRAPHS 1024

typedef unsigned long long u64;

// ---------------- scratch (device globals; no allocations allowed) ----------
struct __align__(16) NodeRec16 {
    __half2 xa;   // x0, x1
    __half2 xb;   // x2, x3
    __half2 pa;   // px, py
    __half2 pb;   // pz, 0
};
__device__ NodeRec16 g_rec[N_NODES];          // 16B per node -> 1 LDG.128 gather
__device__ float4    g_agg[N_NODES * 4];      // Σ silu(hid): (N_NODES, 16) f32
__device__ float     g_cnt[N_NODES];          // edge counts
__device__ float4    g_pooled[NUM_GRAPHS * 8];// pooled: (NUM_GRAPHS, 2, 16)

// ---------------- packed f32x2 helpers (Blackwell FFMA2 path) ----------------
__device__ __forceinline__ u64 pack2(float lo, float hi) {
    u64 r; asm("mov.b64 %0, {%1,%2};" : "=l"(r) : "f"(lo), "f"(hi)); return r;
}
__device__ __forceinline__ void unpack2(u64 v, float& lo, float& hi) {
    asm("mov.b64 {%0,%1}, %2;" : "=f"(lo), "=f"(hi) : "l"(v));
}
__device__ __forceinline__ u64 fma2(u64 a, u64 b, u64 c) {
    u64 d; asm("fma.rn.f32x2 %0, %1, %2, %3;" : "=l"(d) : "l"(a), "l"(b), "l"(c)); return d;
}

// SiLU via single-MUFU tanh: silu(u) = 0.5u * (1 + tanh(u/2))
__device__ __forceinline__ float silu_f(float u) {
    float hu = 0.5f * u;
    float th; asm("tanh.approx.f32 %0, %1;" : "=f"(th) : "f"(hu));
    return fmaf(hu, th, hu);
}

// ---------------- vector reduction helpers (sm_90+ red.v4) ------------------
__device__ __forceinline__ void red_add_v4(float4* addr, float a, float b, float c, float d) {
    asm volatile("red.global.add.v4.f32 [%0], {%1,%2,%3,%4};"
                 :: "l"(addr), "f"(a), "f"(b), "f"(c), "f"(d) : "memory");
}
__device__ __forceinline__ void red_add_f(float* addr, float v) {
    asm volatile("red.global.add.f32 [%0], %1;" :: "l"(addr), "f"(v) : "memory");
}

// ---------------- kernel 0: build fp16 record + zero agg/cnt/pooled ----------
__global__ void __launch_bounds__(256) pre_kernel(
    const float* __restrict__ x, const float* __restrict__ pos)
{
    int n = blockIdx.x * 256 + threadIdx.x;
    if (n >= N_NODES) return;
    float4 xv = reinterpret_cast<const float4*>(x)[n];
    NodeRec16 r;
    r.xa = __floats2half2_rn(xv.x, xv.y);
    r.xb = __floats2half2_rn(xv.z, xv.w);
    r.pa = __floats2half2_rn(pos[3 * n + 0], pos[3 * n + 1]);
    r.pb = __floats2half2_rn(pos[3 * n + 2], 0.f);
    g_rec[n] = r;

    const float4 z = make_float4(0.f, 0.f, 0.f, 0.f);
#pragma unroll
    for (int k = 0; k < 4; k++) g_agg[n * 4 + k] = z;
    g_cnt[n] = 0.f;
    if (n < NUM_GRAPHS * 8) g_pooled[n] = z;
}

// ---------------- kernel 1: edge layer1+SiLU + scatter -----------------------
// Scatters Σ silu(hid) only; W2 applied node-side (linearity).
__global__ void __launch_bounds__(256) edge_kernel(
    const int* __restrict__ ei,
    const float* __restrict__ w1, const float* __restrict__ b1)
{
    __shared__ u64 sw1p[72];   // 9 rows x 8 channel-pairs
    __shared__ u64 sb1p[8];

    int t = threadIdx.x;
    if (t < 72)                sw1p[t]      = pack2(w1[2 * t],        w1[2 * t + 1]);
    else if (t < 80)           sb1p[t - 72] = pack2(b1[2 * (t - 72)], b1[2 * (t - 72) + 1]);
    __syncthreads();

    int e = blockIdx.x * 256 + t;
    if (e >= N_EDGES) return;

    int s = ei[e];
    int d = ei[N_EDGES + e];

    // one 16B load per node
    NodeRec16 rs = g_rec[s];
    NodeRec16 rd = g_rec[d];

    float2 xs01 = __half22float2(rs.xa);
    float2 xs23 = __half22float2(rs.xb);
    float2 ps01 = __half22float2(rs.pa);
    float  psz  = __half2float(__low2half(rs.pb));
    float2 xd01 = __half22float2(rd.xa);
    float2 xd23 = __half22float2(rd.xb);
    float2 pd01 = __half22float2(rd.pa);
    float  pdz  = __half2float(__low2half(rd.pb));

    float rx = ps01.x - pd01.x;
    float ry = ps01.y - pd01.y;
    float rz = psz    - pdz;
    float dist = sqrtf(fmaf(rx, rx, fmaf(ry, ry, rz * rz)));

    float feat[9];
    feat[0] = xd01.x; feat[1] = xd01.y; feat[2] = xd23.x; feat[3] = xd23.y;
    feat[4] = xs01.x; feat[5] = xs01.y; feat[6] = xs23.x; feat[7] = xs23.y;
    feat[8] = dist;

    // layer 1: 72 FFMA2
    u64 acc[8];
#pragma unroll
    for (int j = 0; j < 8; j++) acc[j] = sb1p[j];
#pragma unroll
    for (int i = 0; i < 9; i++) {
        u64 ff = pack2(feat[i], feat[i]);
#pragma unroll
        for (int j = 0; j < 8; j++) acc[j] = fma2(ff, sw1p[i * 8 + j], acc[j]);
    }

    // SiLU (single MUFU each)
    float h[16];
#pragma unroll
    for (int k = 0; k < 8; k++) {
        float a, b;
        unpack2(acc[k], a, b);
        h[2 * k + 0] = silu_f(a);
        h[2 * k + 1] = silu_f(b);
    }

    float4* aggp = &g_agg[d * 4];
    red_add_v4(aggp + 0, h[0],  h[1],  h[2],  h[3]);
    red_add_v4(aggp + 1, h[4],  h[5],  h[6],  h[7]);
    red_add_v4(aggp + 2, h[8],  h[9],  h[10], h[11]);
    red_add_v4(aggp + 3, h[12], h[13], h[14], h[15]);
    red_add_f(&g_cnt[d], 1.0f);
}

// ---------------- kernel 2: node W2 + mean/relu + softmax + pooling ----------
__global__ void __launch_bounds__(256) node_kernel(
    const int* __restrict__ batch,
    const float* __restrict__ w2, const float* __restrict__ b2,
    const float* __restrict__ pool_w, const float* __restrict__ pool_b,
    float* __restrict__ out_s)
{
    __shared__ u64 sw2p[128];   // 16 rows x 8 channel-pairs (row-major w2)
    __shared__ u64 sb2p[8];

    int t = threadIdx.x;
    if (t < 128)               sw2p[t]       = pack2(w2[2 * t],         w2[2 * t + 1]);
    else if (t < 136)          sb2p[t - 128] = pack2(b2[2 * (t - 128)], b2[2 * (t - 128) + 1]);
    __syncthreads();

    int n = blockIdx.x * blockDim.x + t;
    if (n >= N_NODES) return;

    float4 a0 = g_agg[n * 4 + 0];
    float4 a1 = g_agg[n * 4 + 1];
    float4 a2 = g_agg[n * 4 + 2];
    float4 a3 = g_agg[n * 4 + 3];
    float S[16] = {a0.x, a0.y, a0.z, a0.w, a1.x, a1.y, a1.z, a1.w,
                   a2.x, a2.y, a2.z, a2.w, a3.x, a3.y, a3.z, a3.w};

    float fc  = g_cnt[n];
    float inv = __frcp_rn(fmaxf(fc, 1.0f));

    // num = S @ W2 + fc * b2  (exact redistribution of per-edge W2)
    u64 facc[8];
    u64 fcp = pack2(fc, fc);
#pragma unroll
    for (int j = 0; j < 8; j++) {
        u64 zz = pack2(0.f, 0.f);
        facc[j] = fma2(fcp, sb2p[j], zz);
    }
#pragma unroll
    for (int i = 0; i < 16; i++) {
        u64 ss = pack2(S[i], S[i]);
#pragma unroll
        for (int j = 0; j < 8; j++) facc[j] = fma2(ss, sw2p[i * 8 + j], facc[j]);
    }

    float h[16];
#pragma unroll
    for (int j = 0; j < 8; j++) {
        float a, b;
        unpack2(facc[j], a, b);
        h[2 * j + 0] = fmaxf(a * inv, 0.f);
        h[2 * j + 1] = fmaxf(b * inv, 0.f);
    }

    float l0 = pool_b[0], l1 = pool_b[1];
#pragma unroll
    for (int i = 0; i < 16; i++) {
        l0 = fmaf(h[i], pool_w[i * 2 + 0], l0);
        l1 = fmaf(h[i], pool_w[i * 2 + 1], l1);
    }
    float mm = fmaxf(l0, l1);
    float e0 = __expf(l0 - mm), e1 = __expf(l1 - mm);
    float is = __frcp_rn(e0 + e1);
    float s0 = e0 * is, s1 = e1 * is;

    reinterpret_cast<float2*>(out_s)[n] = make_float2(s0, s1);

    int g = batch[n];
    const unsigned full = 0xffffffffu;
    int g0 = __shfl_sync(full, g, 0);
    bool uni = __all_sync(full, g == g0);

    float v[32];
#pragma unroll
    for (int i = 0; i < 16; i++) { v[i] = s0 * h[i]; v[16 + i] = s1 * h[i]; }

    if (uni) {
#pragma unroll
        for (int j = 0; j < 32; j++) {
            float sv = v[j];
            sv += __shfl_xor_sync(full, sv, 16);
            sv += __shfl_xor_sync(full, sv, 8);
            sv += __shfl_xor_sync(full, sv, 4);
            sv += __shfl_xor_sync(full, sv, 2);
            sv += __shfl_xor_sync(full, sv, 1);
            v[j] = sv;
        }
        int lane = t & 31;
        float4* pp = &g_pooled[g0 * 8];
        switch (lane) {
            case 0: red_add_v4(pp + 0, v[0],  v[1],  v[2],  v[3]);  break;
            case 1: red_add_v4(pp + 1, v[4],  v[5],  v[6],  v[7]);  break;
            case 2: red_add_v4(pp + 2, v[8],  v[9],  v[10], v[11]); break;
            case 3: red_add_v4(pp + 3, v[12], v[13], v[14], v[15]); break;
            case 4: red_add_v4(pp + 4, v[16], v[17], v[18], v[19]); break;
            case 5: red_add_v4(pp + 5, v[20], v[21], v[22], v[23]); break;
            case 6: red_add_v4(pp + 6, v[24], v[25], v[26], v[27]); break;
            case 7: red_add_v4(pp + 7, v[28], v[29], v[30], v[31]); break;
            default: break;
        }
    } else {
        float4* pp = &g_pooled[g * 8];
        red_add_v4(pp + 0, v[0],  v[1],  v[2],  v[3]);
        red_add_v4(pp + 1, v[4],  v[5],  v[6],  v[7]);
        red_add_v4(pp + 2, v[8],  v[9],  v[10], v[11]);
        red_add_v4(pp + 3, v[12], v[13], v[14], v[15]);
        red_add_v4(pp + 4, v[16], v[17], v[18], v[19]);
        red_add_v4(pp + 5, v[20], v[21], v[22], v[23]);
        red_add_v4(pp + 6, v[24], v[25], v[26], v[27]);
        red_add_v4(pp + 7, v[28], v[29], v[30], v[31]);
    }
}

// ---------------- kernel 3: per-graph head (one warp per graph) -------------
__global__ void __launch_bounds__(32) graph_kernel(
    const float* __restrict__ toz_w, const float* __restrict__ toz_b,
    const float* __restrict__ vp_w1, const float* __restrict__ vp_b1,
    const float* __restrict__ vp_w2, const float* __restrict__ vp_b2,
    const float* __restrict__ bridge_w, const float* __restrict__ bridge_b,
    float* __restrict__ out_recon,   // (1024, 8, 4)
    float* __restrict__ out_z,       // (1024, 2, 4)
    float* __restrict__ out_forces,  // (1024, 2, 2)
    float* __restrict__ out_V)       // (1024, 1)
{
    const unsigned full = 0xffffffffu;
    int g = blockIdx.x;
    int l = threadIdx.x;
    int k = l >> 4;
    int idx = l & 15;

    float p = reinterpret_cast<const float*>(&g_pooled[g * 8])[l];

    float z[8];
#pragma unroll
    for (int c = 0; c < 4; c++) {
        float prod = p * toz_w[idx * 4 + c];
        prod += __shfl_xor_sync(full, prod, 8);
        prod += __shfl_xor_sync(full, prod, 4);
        prod += __shfl_xor_sync(full, prod, 2);
        prod += __shfl_xor_sync(full, prod, 1);
        float zo = prod + toz_b[c];
        float zx = __shfl_xor_sync(full, zo, 16);
        z[k * 4 + c] = zo;
        z[(1 - k) * 4 + c] = zx;
    }

    if (l < 8) out_z[g * 8 + l] = z[l];

    {
        float acc = bridge_b[l];
#pragma unroll
        for (int i = 0; i < 8; i++)
            acc = fmaf(z[i], bridge_w[i * 32 + l], acc);
        out_recon[g * 32 + l] = acc;
    }

    float dx = z[0] - z[4];
    float dy = z[1] - z[5];
    float dist = sqrtf(dx * dx + dy * dy + 1e-6f);

    float w1 = vp_w1[l];
    float w2 = vp_w2[l];
    float tt = fmaf(dist, w1, vp_b1[l]);
    float u  = __expf(-fabsf(tt));
    float sp = fmaxf(tt, 0.f) + __logf(1.f + u);
    float Vp = sp * w2;
    float sig = __frcp_rn(1.f + __expf(-tt));
    float fpp = sig * w1 * w2;

#pragma unroll
    for (int off = 16; off >= 1; off >>= 1) {
        Vp  += __shfl_xor_sync(full, Vp,  off);
        fpp += __shfl_xor_sync(full, fpp, off);
    }

    if (l == 0) {
        float c = fpp / dist;
        out_forces[g * 4 + 0] = -c * dx;
        out_forces[g * 4 + 1] = -c * dy;
        out_forces[g * 4 + 2] =  c * dx;
        out_forces[g * 4 + 3] =  c * dy;
        out_V[g] = Vp + vp_b2[0];
    }
}

// ---------------- launch -----------------------------------------------------
extern "C" void kernel_launch(void* const* d_in, const int* in_sizes, int n_in,
                              void* d_out, int out_size)
{
    const float* x        = (const float*)d_in[0];
    const float* pos      = (const float*)d_in[1];
    const int*   ei       = (const int*)  d_in[2];
    const int*   batch    = (const int*)  d_in[3];
    const float* enc_w1   = (const float*)d_in[4];
    const float* enc_b1   = (const float*)d_in[5];
    const float* enc_w2   = (const float*)d_in[6];
    const float* enc_b2   = (const float*)d_in[7];
    const float* pool_w   = (const float*)d_in[8];
    const float* pool_b   = (const float*)d_in[9];
    const float* toz_w    = (const float*)d_in[10];
    const float* toz_b    = (const float*)d_in[11];
    const float* vp_w1    = (const float*)d_in[12];
    const float* vp_b1    = (const float*)d_in[13];
    const float* vp_w2    = (const float*)d_in[14];
    const float* vp_b2    = (const float*)d_in[15];
    const float* bridge_w = (const float*)d_in[16];
    const float* bridge_b = (const float*)d_in[17];

    float* out = (float*)d_out;
    float* out_recon  = out;                 // 1024*8*4 = 32768
    float* out_z      = out + 32768;         // 1024*2*4 =  8192
    float* out_s      = out + 40960;         // 262144*2 = 524288
    float* out_forces = out + 565248;        // 1024*2*2 =  4096
    float* out_V      = out + 569344;        // 1024

    pre_kernel<<<N_NODES / 256, 256>>>(x, pos);

    edge_kernel<<<N_EDGES / 256, 256>>>(ei, enc_w1, enc_b1);

    node_kernel<<<N_NODES / 256, 256>>>(batch, enc_w2, enc_b2, pool_w, pool_b, out_s);

    graph_kernel<<<NUM_GRAPHS, 32>>>(toz_w, toz_b, vp_w1, vp_b1, vp_w2, vp_b2,
                                     bridge_w, bridge_b,
                                     out_recon, out_z, out_forces, out_V);
}